// round 7
// baseline (speedup 1.0000x reference)
#include <cuda_runtime.h>
#include <cuda_bf16.h>
#include <cstdint>

// Problem constants (ISNELayer: N=100000 nodes, H=128, E=625000 edges)
#define MAX_N 100000
#define MAX_E 625000
#define H 128
#define H4 (H / 4)        // 32 float4 per row (1 float4 per lane)
#define BCAP 32           // bucket capacity per node; P(Poisson(6.25) > 32) ~ 1e-18
#define OVF_CAP 65536

// Scratch (static device arrays; no cudaMalloc allowed).
// __device__ globals are ZERO-INITIALIZED at module load; k_gather re-zeroes
// the counts it consumed, so every kernel_launch starts from zeroed state.
// g_counts[0..MAX_N-1] = per-target degree; g_counts[MAX_N] = overflow cursor.
__device__ int g_counts[MAX_N + 1];
__device__ int g_bucket[(size_t)MAX_N * BCAP];   // 12.8 MB
__device__ int g_ovf_src[OVF_CAP];
__device__ int g_ovf_tgt[OVF_CAP];

// Packed f32x2 helpers (Blackwell-native; ptxas will not auto-fuse these)
__device__ __forceinline__ void addf32x2(unsigned long long& a, unsigned long long b) {
    asm("add.rn.f32x2 %0, %1, %2;" : "=l"(a) : "l"(a), "l"(b));
}
__device__ __forceinline__ void mulf32x2(unsigned long long& a, unsigned long long b) {
    asm("mul.rn.f32x2 %0, %1, %2;" : "=l"(a) : "l"(a), "l"(b));
}

// ---------------------------------------------------------------------------
// Kernel 1: fill buckets — 2 edges per thread (int2 index loads). 2 edges
// keeps per-thread MLP adequate while doubling thread count vs 4/thread:
// 312k threads ~= one full resident wave, hiding ATOMG (~318 cyc) latency.
__global__ void k_fill(const int* __restrict__ node_ids,
                       const int2* __restrict__ e_src2,
                       const int2* __restrict__ e_tgt2,
                       int e2) {            // e2 = e/2
    int i = blockIdx.x * blockDim.x + threadIdx.x;
    if (i >= e2) return;
    int2 s2 = e_src2[i];
    int2 t2 = e_tgt2[i];
    int src[2] = { node_ids[s2.x], node_ids[s2.y] };
    int tgt[2] = { t2.x, t2.y };
    #pragma unroll
    for (int j = 0; j < 2; j++) {
        int t = tgt[j];
        int pos = atomicAdd(&g_counts[t], 1);
        if (pos < BCAP) {
            g_bucket[t * BCAP + pos] = src[j];
        } else {
            int oi = atomicAdd(&g_counts[MAX_N], 1);
            if (oi < OVF_CAP) { g_ovf_src[oi] = src[j]; g_ovf_tgt[oi] = t; }
        }
    }
}

// ---------------------------------------------------------------------------
// Kernel 2: persistent-warp gather, one-node software pipeline, packed f32x2
// accumulation. Lane l owns bytes [16l, 16l+16) of each node's 512B row,
// loaded as ulonglong2 (two f32x2 pairs) and accumulated with add.rn.f32x2:
// inner loop is SHFL + IMAD + LDG.128 + 2 packed adds (5 instr/edge-lane).
__global__ void __launch_bounds__(256, 8)
k_gather(const char* __restrict__ emb,
         char* __restrict__ out,
         int n, int nwarps) {
    int gtid = blockIdx.x * blockDim.x + threadIdx.x;
    int warp = gtid >> 5;
    int lane = threadIdx.x & 31;

    if (gtid == 0) g_counts[MAX_N] = 0;   // reset overflow cursor for next run

    int node = warp;
    if (node >= n) return;

    const char* lanebase = emb + lane * 16;   // loop-invariant lane offset

    // Prologue for the first node (independent loads, issue back-to-back).
    int deg_all = g_counts[node];
    int my_src  = g_bucket[node * BCAP + lane];

    while (true) {
        int next = node + nwarps;

        // Prefetch next node's metadata BEFORE accumulating the current one.
        int deg_nxt = 0, src_nxt = 0;
        if (next < n) {
            deg_nxt = g_counts[next];
            src_nxt = g_bucket[next * BCAP + lane];
        }

        int deg = deg_all < BCAP ? deg_all : BCAP;
        unsigned long long acc01 = 0ull, acc23 = 0ull;   // packed f32x2 pairs
        #pragma unroll 4
        for (int k = 0; k < deg; k++) {
            int s = __shfl_sync(0xFFFFFFFFu, my_src, k);
            ulonglong2 v = __ldg((const ulonglong2*)(lanebase + (size_t)s * 512));
            addf32x2(acc01, v.x);
            addf32x2(acc23, v.y);
        }

        // Overflow path: only if some node exceeded BCAP (P ~ 1e-18).
        if (deg_all > BCAP) {
            for (int i = 0; i < OVF_CAP; i++) {
                if (i >= deg_all) break;
                if (g_ovf_tgt[i] == node) {
                    int s = g_ovf_src[i];
                    ulonglong2 v = __ldg((const ulonglong2*)(lanebase + (size_t)s * 512));
                    addf32x2(acc01, v.x);
                    addf32x2(acc23, v.y);
                }
            }
        }

        float inv = 1.0f / (float)(deg_all > 1 ? deg_all : 1);
        unsigned long long inv2;
        asm("mov.b64 %0, {%1, %1};" : "=l"(inv2) : "f"(inv));
        mulf32x2(acc01, inv2);
        mulf32x2(acc23, inv2);

        *(ulonglong2*)(out + (size_t)node * 512 + lane * 16) =
            make_ulonglong2(acc01, acc23);               // STG.128

        if (lane == 0) g_counts[node] = 0;   // self-reset (replaces memset)

        if (next >= n) break;
        node = next;
        deg_all = deg_nxt;
        my_src  = src_nxt;
    }
}

// ---------------------------------------------------------------------------
extern "C" void kernel_launch(void* const* d_in, const int* in_sizes, int n_in,
                              void* d_out, int out_size) {
    const int*   node_ids = (const int*)d_in[0];   // [N] int32
    const int*   edge     = (const int*)d_in[1];   // [2, E] int32
    const float* emb      = (const float*)d_in[2]; // [N, H] fp32
    float*       out      = (float*)d_out;         // [N, H] fp32

    int n = in_sizes[0];
    int e = in_sizes[1] / 2;
    if (n > MAX_N) n = MAX_N;
    if (e > MAX_E) e = MAX_E;

    const int* e_src = edge;       // edge_index[0]
    const int* e_tgt = edge + e;   // edge_index[1]

    const int T = 256;

    // Fill: 2 edges/thread (E even; both halves 8B-aligned).
    int e2 = e / 2;
    k_fill<<<(e2 + T - 1) / T, T>>>(node_ids, (const int2*)e_src,
                                    (const int2*)e_tgt, e2);

    // Persistent gather: one full resident wave (148 SMs x 8 blocks/SM).
    {
        int blocks = 148 * 8;
        int nwarps = blocks * (T / 32);
        k_gather<<<blocks, T>>>((const char*)emb, (char*)out, n, nwarps);
    }
}